// round 15
// baseline (speedup 1.0000x reference)
#include <cuda_runtime.h>
#include <cstdint>

constexpr int Bc = 32;
constexpr int Hc = 512;
constexpr int Wc = 512;
constexpr int Pc = 100000;
constexpr long long Nc = (long long)Bc * Pc;   // 3,200,000 points
constexpr int BDIM  = 256;
constexpr int PPT   = 4;                       // points per thread per ticket
constexpr int GRID  = 148 * 4;                 // persistent, one wave at 4 CTAs/SM
constexpr int TPTS  = 32 * PPT;                // 128 points per warp-ticket
constexpr int NT    = (int)(Nc / TPTS);        // 25,000 tickets
static_assert(Nc % TPTS == 0, "tickets tile exactly");
static_assert(Pc % PPT == 0, "4 consecutive points always share a batch index");

__device__ float    g_zero   = 0.0f;  // source for the zero-init memcpy nodes
__device__ unsigned g_ticket = 0;     // warp work-stealing counter

__device__ __forceinline__ float point_loss(float zA, float zB, int o) {
    float d  = zA - zB;
    float gt = (float)o - 1.0f;          // in {-1, 0, +1}
    float sm = log1pf(expf(-gt * d));    // soft-margin branch (gt = +/-1)
    return (o == 1) ? (d * d) : sm;
}

__device__ __forceinline__ int4 ldcs4(const int* p) {
    return __ldcs(reinterpret_cast<const int4*>(p));
}

struct Chunk { int4 xa, ya, xb, yb, o4; };

__device__ __forceinline__ Chunk load_chunk(const int* xA, const int* yA,
                                            const int* xB, const int* yB,
                                            const int* ord, long long base) {
    Chunk c;
    c.xa = ldcs4(xA + base);
    c.ya = ldcs4(yA + base);
    c.xb = ldcs4(xB + base);
    c.yb = ldcs4(yB + base);
    c.o4 = ldcs4(ord + base);
    return c;
}

__global__ __launch_bounds__(BDIM)
void loss_kernel(const float* __restrict__ img,
                 const int* __restrict__ xA,
                 const int* __restrict__ yA,
                 const int* __restrict__ xB,
                 const int* __restrict__ yB,
                 const int* __restrict__ ord,
                 float* __restrict__ out)
{
    const int tid  = threadIdx.x;
    const int lane = tid & 31;

    // Prologue: warp grabs its first ticket (lane 0), broadcast via shfl.
    unsigned t0 = 0;
    if (lane == 0) t0 = atomicAdd(&g_ticket, 1u);
    unsigned t = __shfl_sync(0xFFFFFFFFu, t0, 0);

    float acc = 0.0f;

    Chunk cur;
    if (t < (unsigned)NT)
        cur = load_chunk(xA, yA, xB, yB, ord,
                         (long long)t * TPTS + lane * PPT);

    while (t < (unsigned)NT) {
        // Issue the atomic for the NEXT ticket immediately; its 300-cycle
        // return overlaps this iteration's gathers. shfl happens later.
        unsigned tn0 = 0;
        if (lane == 0) tn0 = atomicAdd(&g_ticket, 1u);

        const long long base = (long long)t * TPTS + lane * PPT;
        const int b = (int)(base / Pc);      // per-thread batch (P % 4 == 0)
        const float* __restrict__ imgb = img + (long long)b * (Hc * Wc);

        // Offsets: y*512 + x
        unsigned offA0 = ((unsigned)cur.ya.x << 9) | (unsigned)cur.xa.x;
        unsigned offA1 = ((unsigned)cur.ya.y << 9) | (unsigned)cur.xa.y;
        unsigned offA2 = ((unsigned)cur.ya.z << 9) | (unsigned)cur.xa.z;
        unsigned offA3 = ((unsigned)cur.ya.w << 9) | (unsigned)cur.xa.w;
        unsigned offB0 = ((unsigned)cur.yb.x << 9) | (unsigned)cur.xb.x;
        unsigned offB1 = ((unsigned)cur.yb.y << 9) | (unsigned)cur.xb.y;
        unsigned offB2 = ((unsigned)cur.yb.z << 9) | (unsigned)cur.xb.z;
        unsigned offB3 = ((unsigned)cur.yb.w << 9) | (unsigned)cur.xb.w;
        int4 o4 = cur.o4;

        // Issue all 8 gathers (current ticket)
        float zA0 = __ldg(imgb + offA0);
        float zA1 = __ldg(imgb + offA1);
        float zA2 = __ldg(imgb + offA2);
        float zA3 = __ldg(imgb + offA3);
        float zB0 = __ldg(imgb + offB0);
        float zB1 = __ldg(imgb + offB1);
        float zB2 = __ldg(imgb + offB2);
        float zB3 = __ldg(imgb + offB3);

        // Broadcast next ticket; prefetch its indices while gathers fly
        unsigned tn = __shfl_sync(0xFFFFFFFFu, tn0, 0);
        if (tn < (unsigned)NT)
            cur = load_chunk(xA, yA, xB, yB, ord,
                             (long long)tn * TPTS + lane * PPT);

        acc += point_loss(zA0, zB0, o4.x)
             + point_loss(zA1, zB1, o4.y)
             + point_loss(zA2, zB2, o4.z)
             + point_loss(zA3, zB3, o4.w);

        t = tn;
    }

    // Warp reduce
    #pragma unroll
    for (int off = 16; off > 0; off >>= 1)
        acc += __shfl_xor_sync(0xFFFFFFFFu, acc, off);

    __shared__ float warp_sums[BDIM / 32];
    int wid = tid >> 5;
    if (lane == 0) warp_sums[wid] = acc;
    __syncthreads();

    if (tid == 0) {
        float v = warp_sums[0];
        #pragma unroll
        for (int w = 1; w < BDIM / 32; w++) v += warp_sums[w];
        // Pre-scaled fire-and-forget reduction straight into the output.
        atomicAdd(out, v * (1.0f / (float)Nc));
    }
}

extern "C" void kernel_launch(void* const* d_in, const int* in_sizes, int n_in,
                              void* d_out, int out_size)
{
    const float* img = (const float*)d_in[0];
    const int*   xA  = (const int*)d_in[1];
    const int*   yA  = (const int*)d_in[2];
    const int*   xB  = (const int*)d_in[3];
    const int*   yB  = (const int*)d_in[4];
    const int*   ord = (const int*)d_in[5];
    float* out = (float*)d_out;

    // Zero-init the (poisoned) output and the ticket counter via cheap
    // D2D memcpy nodes, ordered before the grid on the same stream.
    void* zero_addr = nullptr;
    cudaGetSymbolAddress(&zero_addr, g_zero);
    void* ticket_addr = nullptr;
    cudaGetSymbolAddress(&ticket_addr, g_ticket);
    cudaMemcpyAsync(out, zero_addr, sizeof(float), cudaMemcpyDeviceToDevice, 0);
    cudaMemcpyAsync(ticket_addr, zero_addr, sizeof(unsigned), cudaMemcpyDeviceToDevice, 0);

    loss_kernel<<<GRID, BDIM>>>(img, xA, yA, xB, yB, ord, out);
}

// round 16
// speedup vs baseline: 1.2731x; 1.2731x over previous
#include <cuda_runtime.h>
#include <cstdint>

constexpr int Bc = 32;
constexpr int Hc = 512;
constexpr int Wc = 512;
constexpr int Pc = 100000;
constexpr long long Nc = (long long)Bc * Pc;   // 3,200,000 points
constexpr int BDIM   = 128;
constexpr int PPT    = 4;                      // points per chunk
constexpr int GRID   = 148 * 5;                // persistent one-wave grid
constexpr int NCHUNK = (int)(Nc / PPT);        // 800,000 chunks
static_assert(Nc % PPT == 0, "chunks tile exactly");
static_assert(Pc % PPT == 0, "4 consecutive points always share a batch index");

__device__ float g_zero = 0.0f;   // source for the zero-init memcpy node

__device__ __forceinline__ float point_loss(float zA, float zB, int o) {
    float d  = zA - zB;
    float gt = (float)o - 1.0f;          // in {-1, 0, +1}
    float sm = log1pf(expf(-gt * d));    // soft-margin branch (gt = +/-1)
    return (o == 1) ? (d * d) : sm;
}

__device__ __forceinline__ int4 ldcs4(const int* p) {
    return __ldcs(reinterpret_cast<const int4*>(p));
}

struct Chunk { int4 xa, ya, xb, yb, o4; };
struct Offs  { unsigned a0,a1,a2,a3,b0,b1,b2,b3; int4 o; };

__device__ __forceinline__ Chunk load_chunk(const int* xA, const int* yA,
                                            const int* xB, const int* yB,
                                            const int* ord, long long base) {
    Chunk c;
    c.xa = ldcs4(xA + base);
    c.ya = ldcs4(yA + base);
    c.xb = ldcs4(xB + base);
    c.yb = ldcs4(yB + base);
    c.o4 = ldcs4(ord + base);
    return c;
}

__device__ __forceinline__ Offs make_offs(const Chunk& c) {
    Offs f;
    f.a0 = ((unsigned)c.ya.x << 9) | (unsigned)c.xa.x;
    f.a1 = ((unsigned)c.ya.y << 9) | (unsigned)c.xa.y;
    f.a2 = ((unsigned)c.ya.z << 9) | (unsigned)c.xa.z;
    f.a3 = ((unsigned)c.ya.w << 9) | (unsigned)c.xa.w;
    f.b0 = ((unsigned)c.yb.x << 9) | (unsigned)c.xb.x;
    f.b1 = ((unsigned)c.yb.y << 9) | (unsigned)c.xb.y;
    f.b2 = ((unsigned)c.yb.z << 9) | (unsigned)c.xb.z;
    f.b3 = ((unsigned)c.yb.w << 9) | (unsigned)c.xb.w;
    f.o  = c.o4;
    return f;
}

__device__ __forceinline__ void gather8(float z[8], const Offs& f,
                                        const float* __restrict__ imgb) {
    z[0] = __ldg(imgb + f.a0);
    z[1] = __ldg(imgb + f.a1);
    z[2] = __ldg(imgb + f.a2);
    z[3] = __ldg(imgb + f.a3);
    z[4] = __ldg(imgb + f.b0);
    z[5] = __ldg(imgb + f.b1);
    z[6] = __ldg(imgb + f.b2);
    z[7] = __ldg(imgb + f.b3);
}

__device__ __forceinline__ float loss4(const float z[8], int4 o) {
    return point_loss(z[0], z[4], o.x)
         + point_loss(z[1], z[5], o.y)
         + point_loss(z[2], z[6], o.z)
         + point_loss(z[3], z[7], o.w);
}

__device__ __forceinline__ const float* img_base(const float* img, int c) {
    int b = (int)(((long long)c * PPT) / Pc);
    return img + (long long)b * (Hc * Wc);
}

__global__ __launch_bounds__(BDIM)
void loss_kernel(const float* __restrict__ img,
                 const int* __restrict__ xA,
                 const int* __restrict__ yA,
                 const int* __restrict__ xB,
                 const int* __restrict__ yB,
                 const int* __restrict__ ord,
                 float* __restrict__ out)
{
    const int gtid   = blockIdx.x * BDIM + threadIdx.x;
    const int stride = GRID * BDIM;

    float acc = 0.0f;

    // Ping-pong pipeline state: slot0 / slot1
    int c0 = gtid;            // slot0 chunk: gathers in flight
    int c1 = c0 + stride;     // slot1 chunk: indices in flight
    Chunk t0, t1;
    Offs  f0, f1;
    float z0[8], z1[8];

    if (c0 < NCHUNK) {
        t0 = load_chunk(xA, yA, xB, yB, ord, (long long)c0 * PPT);
        f0 = make_offs(t0);
        gather8(z0, f0, img_base(img, c0));
    }
    if (c1 < NCHUNK)
        t1 = load_chunk(xA, yA, xB, yB, ord, (long long)c1 * PPT);

    while (c0 < NCHUNK) {
        // Phase A: issue gathers for c1 (slot1), prefetch idx c2 -> t0,
        //          consume c0 (slot0) whose gathers were issued last phase.
        int c2 = c1 + stride;
        if (c1 < NCHUNK) { f1 = make_offs(t1); gather8(z1, f1, img_base(img, c1)); }
        if (c2 < NCHUNK) t0 = load_chunk(xA, yA, xB, yB, ord, (long long)c2 * PPT);
        acc += loss4(z0, f0.o);
        c0 = c1; c1 = c2;
        if (c0 >= NCHUNK) break;

        // Phase B: roles swapped (slot0 <-> slot1), no register copies.
        c2 = c1 + stride;
        if (c1 < NCHUNK) { f0 = make_offs(t0); gather8(z0, f0, img_base(img, c1)); }
        if (c2 < NCHUNK) t1 = load_chunk(xA, yA, xB, yB, ord, (long long)c2 * PPT);
        acc += loss4(z1, f1.o);
        c0 = c1; c1 = c2;
    }

    // Warp reduce
    #pragma unroll
    for (int off = 16; off > 0; off >>= 1)
        acc += __shfl_xor_sync(0xFFFFFFFFu, acc, off);

    __shared__ float warp_sums[BDIM / 32];
    int lane = threadIdx.x & 31;
    int wid  = threadIdx.x >> 5;
    if (lane == 0) warp_sums[wid] = acc;
    __syncthreads();

    if (threadIdx.x == 0) {
        float v = warp_sums[0];
        #pragma unroll
        for (int w = 1; w < BDIM / 32; w++) v += warp_sums[w];
        // Pre-scaled fire-and-forget reduction straight into the output.
        atomicAdd(out, v * (1.0f / (float)Nc));
    }
}

extern "C" void kernel_launch(void* const* d_in, const int* in_sizes, int n_in,
                              void* d_out, int out_size)
{
    const float* img = (const float*)d_in[0];
    const int*   xA  = (const int*)d_in[1];
    const int*   yA  = (const int*)d_in[2];
    const int*   xB  = (const int*)d_in[3];
    const int*   yB  = (const int*)d_in[4];
    const int*   ord = (const int*)d_in[5];
    float* out = (float*)d_out;

    // Zero-init the (poisoned) output via a cheap D2D memcpy node.
    void* zero_addr = nullptr;
    cudaGetSymbolAddress(&zero_addr, g_zero);
    cudaMemcpyAsync(out, zero_addr, sizeof(float), cudaMemcpyDeviceToDevice, 0);

    loss_kernel<<<GRID, BDIM>>>(img, xA, yA, xB, yB, ord, out);
}

// round 17
// speedup vs baseline: 1.2917x; 1.0146x over previous
#include <cuda_runtime.h>
#include <cstdint>

constexpr int Bc = 32;
constexpr int Hc = 512;
constexpr int Wc = 512;
constexpr int Pc = 100000;
constexpr long long Nc = (long long)Bc * Pc;   // 3,200,000 points
constexpr int BDIM   = 256;
constexpr int PPT    = 4;                      // points per chunk
constexpr int GRID   = 148 * 4;                // persistent, one wave at 4 CTAs/SM
constexpr int NCHUNK = (int)(Nc / PPT);        // 800,000 chunks
constexpr unsigned CHUNKS_PER_B = Pc / PPT;    // 25,000 chunks per batch image
static_assert(Nc % PPT == 0, "chunks tile exactly");
static_assert(Pc % PPT == 0, "4 consecutive points always share a batch index");

__device__ float g_zero = 0.0f;   // source for the zero-init memcpy node

__device__ __forceinline__ float point_loss(float zA, float zB, int o) {
    float d  = zA - zB;
    float gt = (float)o - 1.0f;          // in {-1, 0, +1}
    float sm = log1pf(expf(-gt * d));    // soft-margin branch (gt = +/-1)
    return (o == 1) ? (d * d) : sm;
}

__device__ __forceinline__ int4 ldcs4(const int* p) {
    return __ldcs(reinterpret_cast<const int4*>(p));
}

struct Chunk { int4 xa, ya, xb, yb, o4; };

__device__ __forceinline__ Chunk load_chunk(const int* xA, const int* yA,
                                            const int* xB, const int* yB,
                                            const int* ord, long long base) {
    Chunk c;
    c.xa = ldcs4(xA + base);
    c.ya = ldcs4(yA + base);
    c.xb = ldcs4(xB + base);
    c.yb = ldcs4(yB + base);
    c.o4 = ldcs4(ord + base);
    return c;
}

__global__ __launch_bounds__(BDIM)
void loss_kernel(const float* __restrict__ img,
                 const int* __restrict__ xA,
                 const int* __restrict__ yA,
                 const int* __restrict__ xB,
                 const int* __restrict__ yB,
                 const int* __restrict__ ord,
                 float* __restrict__ out)
{
    const int gtid   = blockIdx.x * BDIM + threadIdx.x;
    const int stride = GRID * BDIM;

    float acc = 0.0f;

    int c = gtid;
    Chunk cur;
    if (c < NCHUNK)
        cur = load_chunk(xA, yA, xB, yB, ord, (long long)c * PPT);

    while (c < NCHUNK) {
        // Cheap 32-bit batch index: b = c / 25000 (mulhi+shift, not 64-bit div)
        const unsigned b = (unsigned)c / CHUNKS_PER_B;
        // imgb = img + b * 512*512  (32-bit shift, 64-bit add once)
        const float* __restrict__ imgb = img + ((size_t)(b << 18));

        // Offsets: y*512 + x
        unsigned offA0 = ((unsigned)cur.ya.x << 9) | (unsigned)cur.xa.x;
        unsigned offA1 = ((unsigned)cur.ya.y << 9) | (unsigned)cur.xa.y;
        unsigned offA2 = ((unsigned)cur.ya.z << 9) | (unsigned)cur.xa.z;
        unsigned offA3 = ((unsigned)cur.ya.w << 9) | (unsigned)cur.xa.w;
        unsigned offB0 = ((unsigned)cur.yb.x << 9) | (unsigned)cur.xb.x;
        unsigned offB1 = ((unsigned)cur.yb.y << 9) | (unsigned)cur.xb.y;
        unsigned offB2 = ((unsigned)cur.yb.z << 9) | (unsigned)cur.xb.z;
        unsigned offB3 = ((unsigned)cur.yb.w << 9) | (unsigned)cur.xb.w;
        int4 o4 = cur.o4;

        // Issue all 8 gathers (current chunk)
        float zA0 = __ldg(imgb + offA0);
        float zA1 = __ldg(imgb + offA1);
        float zA2 = __ldg(imgb + offA2);
        float zA3 = __ldg(imgb + offA3);
        float zB0 = __ldg(imgb + offB0);
        float zB1 = __ldg(imgb + offB1);
        float zB2 = __ldg(imgb + offB2);
        float zB3 = __ldg(imgb + offB3);

        // Prefetch next chunk's indices — overlaps with the gathers above
        const int cn = c + stride;
        if (cn < NCHUNK)
            cur = load_chunk(xA, yA, xB, yB, ord, (long long)cn * PPT);

        acc += point_loss(zA0, zB0, o4.x)
             + point_loss(zA1, zB1, o4.y)
             + point_loss(zA2, zB2, o4.z)
             + point_loss(zA3, zB3, o4.w);

        c = cn;
    }

    // Warp reduce
    #pragma unroll
    for (int off = 16; off > 0; off >>= 1)
        acc += __shfl_xor_sync(0xFFFFFFFFu, acc, off);

    __shared__ float warp_sums[BDIM / 32];
    int lane = threadIdx.x & 31;
    int wid  = threadIdx.x >> 5;
    if (lane == 0) warp_sums[wid] = acc;
    __syncthreads();

    if (threadIdx.x == 0) {
        float v = warp_sums[0];
        #pragma unroll
        for (int w = 1; w < BDIM / 32; w++) v += warp_sums[w];
        // Pre-scaled fire-and-forget reduction straight into the output.
        atomicAdd(out, v * (1.0f / (float)Nc));
    }
}

extern "C" void kernel_launch(void* const* d_in, const int* in_sizes, int n_in,
                              void* d_out, int out_size)
{
    const float* img = (const float*)d_in[0];
    const int*   xA  = (const int*)d_in[1];
    const int*   yA  = (const int*)d_in[2];
    const int*   xB  = (const int*)d_in[3];
    const int*   yB  = (const int*)d_in[4];
    const int*   ord = (const int*)d_in[5];
    float* out = (float*)d_out;

    // Zero-init the (poisoned) output via a cheap D2D memcpy node.
    void* zero_addr = nullptr;
    cudaGetSymbolAddress(&zero_addr, g_zero);
    cudaMemcpyAsync(out, zero_addr, sizeof(float), cudaMemcpyDeviceToDevice, 0);

    loss_kernel<<<GRID, BDIM>>>(img, xA, yA, xB, yB, ord, out);
}